// round 1
// baseline (speedup 1.0000x reference)
#include <cuda_runtime.h>
#include <math.h>

// Problem constants
// B=128, C=256, H=W=24 (HW=576), Cin_concat=512, taps=9, K_total=4608
// out = prop (128,256,24,24) float32

// ---------------- scratch (static device allocations; allowed) ----------------
__device__ float g_wt[9 * 512 * 256];      // transposed w1: [tap][cin][cout]
__device__ float g_scale[256];             // folded BN scale
__device__ float g_shift[256];             // folded BN shift (incl. b1)
__device__ float g_x1[128 * 256 * 576];    // conv1 -> BN -> ReLU output (NCHW)
__device__ float g_kmap[128 * 25 * 576];   // softmax maps

// ---------------- kernel 1: weight transpose + BN fold ----------------
__global__ void prep_kernel(const float* __restrict__ w1, const float* __restrict__ b1,
                            const float* __restrict__ gam, const float* __restrict__ bet,
                            const float* __restrict__ mu,  const float* __restrict__ var) {
    int idx = blockIdx.x * 256 + threadIdx.x;
    if (idx < 9 * 512 * 256) {
        int o   = idx & 255;          // cout
        int i   = (idx >> 8) & 511;   // cin
        int tap = idx >> 17;          // ky*3+kx
        g_wt[idx] = w1[(o * 512 + i) * 9 + tap];
    }
    if (idx < 256) {
        float inv = gam[idx] / sqrtf(var[idx] + 1e-5f);
        g_scale[idx] = inv;
        g_shift[idx] = bet[idx] + (b1[idx] - mu[idx]) * inv;
    }
}

// ---------------- kernel 2: conv1 (3x3 pad1, 512->256) implicit GEMM ----------------
// M = 73728 (b*576+pos), N = 256, K = 9*512. Tile 128x128x8, 256 threads, 8x8/thread.
__global__ __launch_bounds__(256, 2) void conv1_kernel(const float* __restrict__ src,
                                                       const float* __restrict__ det) {
    __shared__ float As[8][132];   // [k][m], padded
    __shared__ float Bs[8][128];   // [k][n]

    const int t     = threadIdx.x;
    const int mbase = blockIdx.x * 128;
    const int nbase = blockIdx.y * 128;

    // staging identity: thread t stages A[m=t&127][k = (t>>7) + 2i] and B[same k][n=t&127]
    const int sm = t & 127;
    const int sk = t >> 7;      // 0 or 1

    const int mg  = mbase + sm;
    const int b   = mg / 576;
    const int pos = mg - b * 576;
    const int yy  = pos / 24;
    const int xx  = pos - yy * 24;

    const int tx = t & 15;      // m micro-tile index
    const int ty = t >> 4;      // n micro-tile index

    float acc[8][8];
#pragma unroll
    for (int i = 0; i < 8; i++)
#pragma unroll
        for (int j = 0; j < 8; j++) acc[i][j] = 0.f;

    for (int tap = 0; tap < 9; ++tap) {
        const int dy = tap / 3 - 1;
        const int dx = tap - (tap / 3) * 3 - 1;
        const int iy = yy + dy;
        const int ix = xx + dx;
        const bool valid = (iy >= 0) && (iy < 24) && (ix >= 0) && (ix < 24);
        const int spoff = valid ? iy * 24 + ix : 0;
        const float* wtp = g_wt + tap * 131072 + nbase + sm;   // n = sm

        for (int kc = 0; kc < 512; kc += 8) {
            const float* inp = (kc < 256) ? src : det;
            const float* ap  = inp + (b * 256 + (kc & 255) + sk) * 576 + spoff;

            float av[4], bv[4];
#pragma unroll
            for (int i = 0; i < 4; i++) {
                av[i] = valid ? ap[i * 1152] : 0.f;      // +2 channels per step
                bv[i] = wtp[(kc + sk + 2 * i) * 256];
            }
            __syncthreads();
#pragma unroll
            for (int i = 0; i < 4; i++) {
                As[sk + 2 * i][sm] = av[i];
                Bs[sk + 2 * i][sm] = bv[i];
            }
            __syncthreads();

#pragma unroll
            for (int kk = 0; kk < 8; kk++) {
                float a[8], bb[8];
                *(float4*)&a[0]  = *(const float4*)&As[kk][tx * 8];
                *(float4*)&a[4]  = *(const float4*)&As[kk][tx * 8 + 4];
                *(float4*)&bb[0] = *(const float4*)&Bs[kk][ty * 8];
                *(float4*)&bb[4] = *(const float4*)&Bs[kk][ty * 8 + 4];
#pragma unroll
                for (int i = 0; i < 8; i++)
#pragma unroll
                    for (int j = 0; j < 8; j++)
                        acc[i][j] = fmaf(a[i], bb[j], acc[i][j]);
            }
        }
    }

    // epilogue: BN fold + ReLU, write to g_x1 (NCHW)
    const int n0 = nbase + ty * 8;
    float sc[8], sh[8];
#pragma unroll
    for (int j = 0; j < 8; j++) { sc[j] = g_scale[n0 + j]; sh[j] = g_shift[n0 + j]; }

#pragma unroll
    for (int i = 0; i < 8; i++) {
        int m  = mbase + tx * 8 + i;
        int bb = m / 576;
        int pp = m - bb * 576;
        float* op = g_x1 + (bb * 256 + n0) * 576 + pp;
#pragma unroll
        for (int j = 0; j < 8; j++) {
            float v = fmaf(acc[i][j], sc[j], sh[j]);
            op[j * 576] = fmaxf(v, 0.f);
        }
    }
}

// ---------------- kernel 3: conv2 (1x1, 256->25) + bias + softmax ----------------
// Each thread owns one spatial position; 25 logits in registers.
__global__ __launch_bounds__(128) void conv2_kernel(const float* __restrict__ w2,
                                                    const float* __restrict__ b2) {
    __shared__ float As[16][128];
    __shared__ float Bs[16][25];
    __shared__ float b2s[25];

    const int t   = threadIdx.x;
    const int m   = blockIdx.x * 128 + t;
    const int b   = m / 576;
    const int pos = m - b * 576;
    const float* xp = g_x1 + b * 147456 + pos;

    if (t < 25) b2s[t] = b2[t];

    float acc[25];
#pragma unroll
    for (int n = 0; n < 25; n++) acc[n] = 0.f;

    for (int kc = 0; kc < 256; kc += 16) {
#pragma unroll
        for (int kk = 0; kk < 16; kk++) As[kk][t] = xp[(kc + kk) * 576];
        for (int e = t; e < 400; e += 128) {
            int k = e / 25;
            int n = e - k * 25;
            Bs[k][n] = w2[n * 256 + kc + k];
        }
        __syncthreads();
#pragma unroll
        for (int kk = 0; kk < 16; kk++) {
            float a = As[kk][t];
#pragma unroll
            for (int n = 0; n < 25; n++) acc[n] = fmaf(a, Bs[kk][n], acc[n]);
        }
        __syncthreads();
    }

    float mx = -1e30f;
#pragma unroll
    for (int n = 0; n < 25; n++) { acc[n] += b2s[n]; mx = fmaxf(mx, acc[n]); }
    float sum = 0.f;
#pragma unroll
    for (int n = 0; n < 25; n++) { acc[n] = __expf(acc[n] - mx); sum += acc[n]; }
    float inv = 1.f / sum;

    float* kp = g_kmap + b * 14400 + pos;
#pragma unroll
    for (int n = 0; n < 25; n++) kp[n * 576] = acc[n] * inv;
}

// ---------------- kernel 4: 25-tap propagation ----------------
// Block = (batch, 8-row group): 192 positions, 192 threads.
// 25 probs per position in registers; per-channel 12x28 padded src patch in smem,
// double buffered (one barrier per channel).
__global__ __launch_bounds__(192) void prop_kernel(const float* __restrict__ src,
                                                   float* __restrict__ out) {
    __shared__ float patch[2][336];   // 12 rows x 28 cols

    const int t    = threadIdx.x;
    const int b    = blockIdx.x / 3;
    const int rg   = blockIdx.x - b * 3;
    const int pos0 = rg * 192;
    const int y0   = rg * 8;

    // 25 probabilities for this position (same (y,x) for all channels)
    float pr[25];
    const float* kp = g_kmap + b * 14400 + pos0 + t;
#pragma unroll
    for (int n = 0; n < 25; n++) pr[n] = kp[n * 576];

    // precompute staging slots: elements e = t, t+192 of the 336-float patch
    int off[2];
    bool val[2];
#pragma unroll
    for (int i = 0; i < 2; i++) {
        int e  = t + i * 192;
        int ry = e / 28;
        int rx = e - ry * 28;
        int iy = y0 - 2 + ry;
        int ix = rx - 2;
        val[i] = (e < 336) && iy >= 0 && iy < 24 && ix >= 0 && ix < 24;
        off[i] = val[i] ? iy * 24 + ix : 0;
    }

    const float* sb = src + b * 147456;
    const int py = t / 24 + 2;
    const int px = t - (t / 24) * 24 + 2;
    const int pcenter = py * 28 + px;
    float* ob = out + b * 147456 + pos0 + t;

    // stage channel 0
#pragma unroll
    for (int i = 0; i < 2; i++) {
        int e = t + i * 192;
        if (e < 336) patch[0][e] = val[i] ? sb[off[i]] : 0.f;
    }
    __syncthreads();

    for (int c = 0; c < 256; ++c) {
        float nv[2];
        if (c + 1 < 256) {
#pragma unroll
            for (int i = 0; i < 2; i++)
                nv[i] = val[i] ? sb[(c + 1) * 576 + off[i]] : 0.f;
        }

        const float* pc = &patch[c & 1][0];
        float sum = 0.f;
#pragma unroll
        for (int o = 0; o < 25; o++) {
            int ddy = o / 5 - 2;
            int ddx = o - (o / 5) * 5 - 2;
            sum = fmaf(pc[pcenter + ddy * 28 + ddx], pr[o], sum);
        }
        ob[c * 576] = sum;

        if (c + 1 < 256) {
#pragma unroll
            for (int i = 0; i < 2; i++) {
                int e = t + i * 192;
                if (e < 336) patch[(c + 1) & 1][e] = nv[i];
            }
        }
        __syncthreads();
    }
}

// ---------------- launcher ----------------
extern "C" void kernel_launch(void* const* d_in, const int* in_sizes, int n_in,
                              void* d_out, int out_size) {
    const float* src = (const float*)d_in[0];
    const float* det = (const float*)d_in[1];
    const float* w1  = (const float*)d_in[2];
    const float* b1  = (const float*)d_in[3];
    const float* gam = (const float*)d_in[4];
    const float* bet = (const float*)d_in[5];
    const float* mu  = (const float*)d_in[6];
    const float* var = (const float*)d_in[7];
    const float* w2  = (const float*)d_in[8];
    const float* b2  = (const float*)d_in[9];
    float* out = (float*)d_out;

    prep_kernel<<<4608, 256>>>(w1, b1, gam, bet, mu, var);

    dim3 g1(576, 2);                       // M tiles x N tiles
    conv1_kernel<<<g1, 256>>>(src, det);

    conv2_kernel<<<576, 128>>>(w2, b2);    // 73728 / 128 positions

    prop_kernel<<<384, 192>>>(src, out);   // 128 batches x 3 row-groups
}

// round 3
// speedup vs baseline: 1.0435x; 1.0435x over previous
#include <cuda_runtime.h>
#include <cuda_bf16.h>
#include <cstdint>
#include <math.h>

// ============================================================================
// B=128, C=256, H=W=24. conv1 3x3 pad1 (512->256) + BN + ReLU -> conv2 1x1
// (256->25) + softmax -> 25-tap weighted propagation.
// conv1 via mma.sync bf16 (HMMA), fp32 emulated with bf16x3 split:
//   A k-layout [hi|lo|hi], B k-layout [Bhi|Bhi|Blo]  => K' = 3*4608 = 13824.
// Padded-plane M layout: 26x26=676 positions/plane, 130 planes (guards).
// ============================================================================

#define NPLANE   676
#define KPRIME   1536              // per-tap k': hi(512)|lo(512)|hi(512)
#define N_CHUNKS 108               // 9 taps * 12 chunks of 128

// ---------------- static device scratch ----------------
__device__ __nv_bfloat16 g_xs[130 * NPLANE * KPRIME];  // padded NHWC bf16x3
__device__ __nv_bfloat16 g_wb[9 * 256 * KPRIME];       // weights [tap][n][k']
__device__ float g_scale[256];
__device__ float g_shift[256];
__device__ float g_x1[128 * 256 * 576];                // conv1 out, NCHW
__device__ float g_kmap[128 * 25 * 576];               // softmax maps

// ---------------- PTX helpers (all plain sm_80/75-era, compute_100-safe) ----
__device__ __forceinline__ uint32_t smem_u32(const void* p) {
    uint32_t a;
    asm("{ .reg .u64 t; cvta.to.shared.u64 t, %1; cvt.u32.u64 %0, t; }" : "=r"(a) : "l"(p));
    return a;
}
#define CP_ASYNC16(dst, src) \
    asm volatile("cp.async.cg.shared.global [%0], [%1], 16;" :: "r"(dst), "l"(src) : "memory")
#define CP_COMMIT() asm volatile("cp.async.commit_group;" ::: "memory")
#define CP_WAIT(n)  asm volatile("cp.async.wait_group %0;" :: "n"(n) : "memory")

__device__ __forceinline__ void ldsm_x4(uint32_t* r, uint32_t addr) {
    asm volatile("ldmatrix.sync.aligned.m8n8.x4.shared.b16 {%0,%1,%2,%3}, [%4];"
                 : "=r"(r[0]), "=r"(r[1]), "=r"(r[2]), "=r"(r[3]) : "r"(addr));
}
__device__ __forceinline__ void ldsm_x2(uint32_t* r, uint32_t addr) {
    asm volatile("ldmatrix.sync.aligned.m8n8.x2.shared.b16 {%0,%1}, [%2];"
                 : "=r"(r[0]), "=r"(r[1]) : "r"(addr));
}
__device__ __forceinline__ void mma_bf16(float* c, const uint32_t* a, const uint32_t* b) {
    asm volatile("mma.sync.aligned.m16n8k16.row.col.f32.bf16.bf16.f32 "
                 "{%0,%1,%2,%3}, {%4,%5,%6,%7}, {%8,%9}, {%0,%1,%2,%3};"
                 : "+f"(c[0]), "+f"(c[1]), "+f"(c[2]), "+f"(c[3])
                 : "r"(a[0]), "r"(a[1]), "r"(a[2]), "r"(a[3]), "r"(b[0]), "r"(b[1]));
}

// ---------------- prep: BN scale/shift fold ----------------
__global__ void snprep_kernel(const float* __restrict__ b1, const float* __restrict__ gam,
                              const float* __restrict__ bet, const float* __restrict__ mu,
                              const float* __restrict__ var) {
    int i = threadIdx.x;
    float inv = gam[i] * rsqrtf(var[i] + 1e-5f);
    g_scale[i] = inv;
    g_shift[i] = bet[i] + (b1[i] - mu[i]) * inv;
}

// ---------------- prep: weights -> bf16 [tap][n][Bhi|Bhi|Blo] ----------------
__global__ void wprep_kernel(const float* __restrict__ w1) {
    int idx = blockIdx.x * 256 + threadIdx.x;
    if (idx >= 9 * 256 * KPRIME) return;
    int kp = idx % KPRIME;
    int rest = idx / KPRIME;
    int n = rest % 256;
    int tap = rest / 256;
    int c = kp < 512 ? kp : (kp < 1024 ? kp - 512 : kp - 1024);
    float v = w1[((size_t)n * 512 + c) * 9 + tap];
    __nv_bfloat16 h = __float2bfloat16(v);
    g_wb[idx] = (kp < 1024) ? h : __float2bfloat16(v - __bfloat162float(h));
}

// ---------------- prep: inputs -> padded NHWC bf16 [hi|lo|hi] ----------------
__global__ __launch_bounds__(256) void xprep_kernel(const float* __restrict__ src,
                                                    const float* __restrict__ det) {
    __shared__ float s[256][25];
    int blk = blockIdx.x;
    int p = blk / 26, yq = blk % 26;
    int t = threadIdx.x;
    __nv_bfloat16* rowout = g_xs + (size_t)(p * NPLANE + yq * 26) * KPRIME;
    bool interior = (p >= 1 && p <= 128 && yq >= 1 && yq <= 24);
    if (!interior) {
        uint4 z = make_uint4(0, 0, 0, 0);
        uint4* o = (uint4*)rowout;
        for (int e = t; e < 26 * KPRIME / 8; e += 256) o[e] = z;
        return;
    }
    int b = p - 1, y = yq - 1;
    {
        uint4 z = make_uint4(0, 0, 0, 0);
        uint4* o0 = (uint4*)rowout;
        uint4* o1 = (uint4*)(rowout + (size_t)25 * KPRIME);
        for (int e = t; e < KPRIME / 8; e += 256) { o0[e] = z; o1[e] = z; }
    }
    for (int pass = 0; pass < 2; ++pass) {
        const float* in = pass ? det : src;
        for (int e = t; e < 256 * 24; e += 256) {
            int ch = e / 24, x = e - ch * 24;
            s[ch][x] = in[((size_t)b * 256 + ch) * 576 + y * 24 + x];
        }
        __syncthreads();
        int cb = pass * 256;
        for (int x = 0; x < 24; ++x) {
            float v = s[t][x];
            __nv_bfloat16 h = __float2bfloat16(v);
            __nv_bfloat16 l = __float2bfloat16(v - __bfloat162float(h));
            __nv_bfloat16* o = rowout + (size_t)(x + 1) * KPRIME;
            o[cb + t] = h;
            o[512 + cb + t] = l;
            o[1024 + cb + t] = h;
        }
        __syncthreads();
    }
}

// ---------------- conv1: 128x128 CTA tile, mma.sync bf16, 3-stage cp.async ----
// SMEM per stage: A 128 rows x 256B = 32KB, B same = 32KB. 3 stages = 192KB.
#define CONV1_SMEM (3 * 65536)

__global__ __launch_bounds__(256) void conv1_mma() {
    extern __shared__ __align__(1024) char smem_raw[];
    const uint32_t sbase = smem_u32(smem_raw);

    const int t = threadIdx.x;
    const int l = t & 31;
    const int w = t >> 5;
    const int m0 = blockIdx.y * 128;        // M tile (y-major => N-halves adjacent)
    const int nbase = blockIdx.x * 128;     // N half

    // ---- staging precompute: thread t -> row t&127, k-half t>>7, 8 granules ----
    const int srow = t & 127;
    const int shalf = t >> 7;
    uint32_t sdst[8];
#pragma unroll
    for (int g = 0; g < 8; g++) {
        int ch = shalf * 8 + g;                              // 16B chunk in row
        sdst[g] = (uint32_t)srow * 256u + (uint32_t)((ch ^ (srow & 7)) * 16);
    }
    const size_t arow_noshift = (size_t)(NPLANE + m0 + srow);

    // ---- compute-side precompute ----
    const int wm = (w >> 2) * 64;            // warp M offset (0/64)
    const int wn = (w & 3) * 32;             // warp N offset (0/32/64/96)
    const int rsw = l & 7;                   // swizzle key (row & 7)
    uint32_t aRow256[4], bRow256[4];
#pragma unroll
    for (int mi = 0; mi < 4; mi++) aRow256[mi] = (uint32_t)(wm + mi * 16 + (l & 15)) * 256u;
#pragma unroll
    for (int ni = 0; ni < 4; ni++) bRow256[ni] = (uint32_t)(wn + ni * 8 + (l & 7)) * 256u;
    const uint32_t aHi = (uint32_t)(l >> 4);         // 0/1
    const uint32_t bHi = (uint32_t)((l >> 3) & 1);   // 0/1

    float acc[4][4][4];
#pragma unroll
    for (int mi = 0; mi < 4; mi++)
#pragma unroll
        for (int ni = 0; ni < 4; ni++)
#pragma unroll
            for (int r = 0; r < 4; r++) acc[mi][ni][r] = 0.f;

    // ---- chunk load issue ----
    auto issue = [&](int c) {
        const int tap = c / 12;
        const int kc = (c - tap * 12) * 128;
        const int ty = tap / 3, tx = tap - ty * 3;
        const int shift = (ty - 1) * 26 + (tx - 1);
        const uint32_t As = sbase + (uint32_t)(c % 3) * 65536u;
        const uint32_t Bs = As + 32768u;
        const __nv_bfloat16* asrc = g_xs + (arow_noshift + shift) * KPRIME + kc + shalf * 64;
        const __nv_bfloat16* bsrc = g_wb + ((size_t)(tap * 256 + nbase + srow)) * KPRIME
                                  + kc + shalf * 64;
#pragma unroll
        for (int g = 0; g < 8; g++) {
            CP_ASYNC16(As + sdst[g], asrc + g * 8);
            CP_ASYNC16(Bs + sdst[g], bsrc + g * 8);
        }
    };

    auto compute = [&](int c) {
        const uint32_t As = sbase + (uint32_t)(c % 3) * 65536u;
        const uint32_t Bs = As + 32768u;
#pragma unroll
        for (int ks = 0; ks < 8; ks++) {
            uint32_t a[4][4], b[4][2];
            const uint32_t ca = (uint32_t)(ks * 2) + aHi;
            const uint32_t cb = (uint32_t)(ks * 2) + bHi;
            const uint32_t aoff = ((ca ^ rsw) << 4);
            const uint32_t boff = ((cb ^ rsw) << 4);
#pragma unroll
            for (int mi = 0; mi < 4; mi++) ldsm_x4(a[mi], As + aRow256[mi] + aoff);
#pragma unroll
            for (int ni = 0; ni < 4; ni++) ldsm_x2(b[ni], Bs + bRow256[ni] + boff);
#pragma unroll
            for (int mi = 0; mi < 4; mi++)
#pragma unroll
                for (int ni = 0; ni < 4; ni++)
                    mma_bf16(acc[mi][ni], a[mi], b[ni]);
        }
    };

    // ---- 3-stage pipeline ----
    issue(0); CP_COMMIT();
    issue(1); CP_COMMIT();
    for (int c = 0; c < N_CHUNKS; ++c) {
        if (c + 2 < N_CHUNKS) { issue(c + 2); CP_COMMIT(); CP_WAIT(2); }
        else if (c + 1 < N_CHUNKS) { CP_WAIT(1); }
        else { CP_WAIT(0); }
        __syncthreads();
        compute(c);
        __syncthreads();
    }

    // ---- epilogue: BN + ReLU, drop padded rows, write g_x1 (NCHW) ----
    bool mvalid[8];
    float* mptr[8];
#pragma unroll
    for (int mi = 0; mi < 4; mi++)
#pragma unroll
        for (int h = 0; h < 2; h++) {
            int i = mi * 2 + h;
            int mg = m0 + wm + mi * 16 + (l >> 2) + h * 8;
            int plane = mg / 676;
            int pos = mg - plane * 676;
            int yq = pos / 26, xq = pos - yq * 26;
            mvalid[i] = (yq >= 1 && yq <= 24 && xq >= 1 && xq <= 24);
            mptr[i] = g_x1 + (size_t)plane * 147456 + (yq - 1) * 24 + (xq - 1);
        }
#pragma unroll
    for (int ni = 0; ni < 4; ni++) {
        int n0 = nbase + wn + ni * 8 + (l & 3) * 2;
        float sc0 = g_scale[n0], sh0 = g_shift[n0];
        float sc1 = g_scale[n0 + 1], sh1 = g_shift[n0 + 1];
#pragma unroll
        for (int mi = 0; mi < 4; mi++)
#pragma unroll
            for (int h = 0; h < 2; h++) {
                int i = mi * 2 + h;
                if (!mvalid[i]) continue;
                float v0 = fmaf(acc[mi][ni][h * 2 + 0], sc0, sh0);
                float v1 = fmaf(acc[mi][ni][h * 2 + 1], sc1, sh1);
                mptr[i][(size_t)n0 * 576] = fmaxf(v0, 0.f);
                mptr[i][(size_t)(n0 + 1) * 576] = fmaxf(v1, 0.f);
            }
    }
}

// ---------------- conv2 (1x1, 256->25) + bias + softmax ----------------
__global__ __launch_bounds__(128) void conv2_kernel(const float* __restrict__ w2,
                                                    const float* __restrict__ b2) {
    __shared__ float As[16][128];
    __shared__ float Bs[16][25];
    __shared__ float b2s[25];

    const int t = threadIdx.x;
    const int m = blockIdx.x * 128 + t;
    const int b = m / 576;
    const int pos = m - b * 576;
    const float* xp = g_x1 + (size_t)b * 147456 + pos;

    if (t < 25) b2s[t] = b2[t];

    float acc[25];
#pragma unroll
    for (int n = 0; n < 25; n++) acc[n] = 0.f;

    for (int kc = 0; kc < 256; kc += 16) {
#pragma unroll
        for (int kk = 0; kk < 16; kk++) As[kk][t] = xp[(size_t)(kc + kk) * 576];
        for (int e = t; e < 400; e += 128) {
            int k = e / 25;
            int n = e - k * 25;
            Bs[k][n] = w2[n * 256 + kc + k];
        }
        __syncthreads();
#pragma unroll
        for (int kk = 0; kk < 16; kk++) {
            float a = As[kk][t];
#pragma unroll
            for (int n = 0; n < 25; n++) acc[n] = fmaf(a, Bs[kk][n], acc[n]);
        }
        __syncthreads();
    }

    float mx = -1e30f;
#pragma unroll
    for (int n = 0; n < 25; n++) { acc[n] += b2s[n]; mx = fmaxf(mx, acc[n]); }
    float sum = 0.f;
#pragma unroll
    for (int n = 0; n < 25; n++) { acc[n] = __expf(acc[n] - mx); sum += acc[n]; }
    float inv = 1.f / sum;

    float* kp = g_kmap + (size_t)b * 14400 + pos;
#pragma unroll
    for (int n = 0; n < 25; n++) kp[(size_t)n * 576] = acc[n] * inv;
}

// ---------------- 25-tap propagation ----------------
__global__ __launch_bounds__(192) void prop_kernel(const float* __restrict__ src,
                                                   float* __restrict__ out) {
    __shared__ float patch[2][336];

    const int t = threadIdx.x;
    const int b = blockIdx.x / 3;
    const int rg = blockIdx.x - b * 3;
    const int pos0 = rg * 192;
    const int y0 = rg * 8;

    float pr[25];
    const float* kp = g_kmap + (size_t)b * 14400 + pos0 + t;
#pragma unroll
    for (int n = 0; n < 25; n++) pr[n] = kp[(size_t)n * 576];

    int off[2];
    bool val[2];
#pragma unroll
    for (int i = 0; i < 2; i++) {
        int e = t + i * 192;
        int ry = e / 28;
        int rx = e - ry * 28;
        int iy = y0 - 2 + ry;
        int ix = rx - 2;
        val[i] = (e < 336) && iy >= 0 && iy < 24 && ix >= 0 && ix < 24;
        off[i] = val[i] ? iy * 24 + ix : 0;
    }

    const float* sb = src + (size_t)b * 147456;
    const int py = t / 24 + 2;
    const int px = t - (t / 24) * 24 + 2;
    const int pcenter = py * 28 + px;
    float* ob = out + (size_t)b * 147456 + pos0 + t;

#pragma unroll
    for (int i = 0; i < 2; i++) {
        int e = t + i * 192;
        if (e < 336) patch[0][e] = val[i] ? sb[off[i]] : 0.f;
    }
    __syncthreads();

    for (int c = 0; c < 256; ++c) {
        float nv[2];
        if (c + 1 < 256) {
#pragma unroll
            for (int i = 0; i < 2; i++)
                nv[i] = val[i] ? sb[(size_t)(c + 1) * 576 + off[i]] : 0.f;
        }
        const float* pc = &patch[c & 1][0];
        float sum = 0.f;
#pragma unroll
        for (int o = 0; o < 25; o++) {
            int ddy = o / 5 - 2;
            int ddx = o - (o / 5) * 5 - 2;
            sum = fmaf(pc[pcenter + ddy * 28 + ddx], pr[o], sum);
        }
        ob[(size_t)c * 576] = sum;

        if (c + 1 < 256) {
#pragma unroll
            for (int i = 0; i < 2; i++) {
                int e = t + i * 192;
                if (e < 336) patch[(c + 1) & 1][e] = nv[i];
            }
        }
        __syncthreads();
    }
}

// ---------------- launcher ----------------
extern "C" void kernel_launch(void* const* d_in, const int* in_sizes, int n_in,
                              void* d_out, int out_size) {
    const float* src = (const float*)d_in[0];
    const float* det = (const float*)d_in[1];
    const float* w1  = (const float*)d_in[2];
    const float* b1  = (const float*)d_in[3];
    const float* gam = (const float*)d_in[4];
    const float* bet = (const float*)d_in[5];
    const float* mu  = (const float*)d_in[6];
    const float* var = (const float*)d_in[7];
    const float* w2  = (const float*)d_in[8];
    const float* b2  = (const float*)d_in[9];
    float* out = (float*)d_out;

    cudaFuncSetAttribute(conv1_mma, cudaFuncAttributeMaxDynamicSharedMemorySize, CONV1_SMEM);

    snprep_kernel<<<1, 256>>>(b1, gam, bet, mu, var);
    wprep_kernel<<<(9 * 256 * KPRIME + 255) / 256, 256>>>(w1);
    xprep_kernel<<<130 * 26, 256>>>(src, det);

    dim3 g1(2, 676);                        // x = N half, y = M tile
    conv1_mma<<<g1, 256, CONV1_SMEM>>>();

    conv2_kernel<<<576, 128>>>(w2, b2);
    prop_kernel<<<384, 192>>>(src, out);
}

// round 4
// speedup vs baseline: 1.1656x; 1.1170x over previous
#include <cuda_runtime.h>
#include <cuda_bf16.h>
#include <cstdint>
#include <math.h>

// ============================================================================
// B=128, C=256, H=W=24. conv1 3x3 pad1 (512->256) + BN + ReLU -> conv2 1x1
// (256->25) + softmax -> 25-tap weighted propagation.
// conv1 via mma.sync bf16 (HMMA), fp32 emulated with bf16x3 split:
//   A k-layout [hi|lo|hi], B k-layout [Bhi|Bhi|Blo]  => K' = 3*4608 = 13824.
// Padded-plane M layout: 26x26=676 positions/plane, 130 planes (guards).
// R4: K-chunk 64 (3x32KB stages, 2 CTA/SM), single sync/chunk, prop re-grid.
// ============================================================================

#define NPLANE   676
#define KPRIME   1536              // per-tap k': hi(512)|lo(512)|hi(512)
#define N_CHUNKS 216               // 9 taps * 24 chunks of 64

// ---------------- static device scratch ----------------
__device__ __nv_bfloat16 g_xs[130 * NPLANE * KPRIME];  // padded NHWC bf16x3
__device__ __nv_bfloat16 g_wb[9 * 256 * KPRIME];       // weights [tap][n][k']
__device__ float g_scale[256];
__device__ float g_shift[256];
__device__ float g_x1[128 * 256 * 576];                // conv1 out, NCHW
__device__ float g_kmap[128 * 25 * 576];               // softmax maps

// ---------------- PTX helpers (plain sm_80-era, compute_100-safe) ----------
__device__ __forceinline__ uint32_t smem_u32(const void* p) {
    uint32_t a;
    asm("{ .reg .u64 t; cvta.to.shared.u64 t, %1; cvt.u32.u64 %0, t; }" : "=r"(a) : "l"(p));
    return a;
}
#define CP_ASYNC16(dst, src) \
    asm volatile("cp.async.cg.shared.global [%0], [%1], 16;" :: "r"(dst), "l"(src) : "memory")
#define CP_COMMIT() asm volatile("cp.async.commit_group;" ::: "memory")
#define CP_WAIT(n)  asm volatile("cp.async.wait_group %0;" :: "n"(n) : "memory")

__device__ __forceinline__ void ldsm_x4(uint32_t* r, uint32_t addr) {
    asm volatile("ldmatrix.sync.aligned.m8n8.x4.shared.b16 {%0,%1,%2,%3}, [%4];"
                 : "=r"(r[0]), "=r"(r[1]), "=r"(r[2]), "=r"(r[3]) : "r"(addr));
}
__device__ __forceinline__ void ldsm_x2(uint32_t* r, uint32_t addr) {
    asm volatile("ldmatrix.sync.aligned.m8n8.x2.shared.b16 {%0,%1}, [%2];"
                 : "=r"(r[0]), "=r"(r[1]) : "r"(addr));
}
__device__ __forceinline__ void mma_bf16(float* c, const uint32_t* a, const uint32_t* b) {
    asm volatile("mma.sync.aligned.m16n8k16.row.col.f32.bf16.bf16.f32 "
                 "{%0,%1,%2,%3}, {%4,%5,%6,%7}, {%8,%9}, {%0,%1,%2,%3};"
                 : "+f"(c[0]), "+f"(c[1]), "+f"(c[2]), "+f"(c[3])
                 : "r"(a[0]), "r"(a[1]), "r"(a[2]), "r"(a[3]), "r"(b[0]), "r"(b[1]));
}

// ---------------- prep: BN scale/shift fold ----------------
__global__ void snprep_kernel(const float* __restrict__ b1, const float* __restrict__ gam,
                              const float* __restrict__ bet, const float* __restrict__ mu,
                              const float* __restrict__ var) {
    int i = threadIdx.x;
    float inv = gam[i] * rsqrtf(var[i] + 1e-5f);
    g_scale[i] = inv;
    g_shift[i] = bet[i] + (b1[i] - mu[i]) * inv;
}

// ---------------- prep: weights -> bf16 [tap][n][Bhi|Bhi|Blo] ----------------
__global__ void wprep_kernel(const float* __restrict__ w1) {
    int idx = blockIdx.x * 256 + threadIdx.x;
    if (idx >= 9 * 256 * KPRIME) return;
    int kp = idx % KPRIME;
    int rest = idx / KPRIME;
    int n = rest % 256;
    int tap = rest / 256;
    int c = kp < 512 ? kp : (kp < 1024 ? kp - 512 : kp - 1024);
    float v = w1[((size_t)n * 512 + c) * 9 + tap];
    __nv_bfloat16 h = __float2bfloat16(v);
    g_wb[idx] = (kp < 1024) ? h : __float2bfloat16(v - __bfloat162float(h));
}

// ---------------- prep: inputs -> padded NHWC bf16 [hi|lo|hi] ----------------
__global__ __launch_bounds__(256) void xprep_kernel(const float* __restrict__ src,
                                                    const float* __restrict__ det) {
    __shared__ float s[256][25];
    int blk = blockIdx.x;
    int p = blk / 26, yq = blk % 26;
    int t = threadIdx.x;
    __nv_bfloat16* rowout = g_xs + (size_t)(p * NPLANE + yq * 26) * KPRIME;
    bool interior = (p >= 1 && p <= 128 && yq >= 1 && yq <= 24);
    if (!interior) {
        uint4 z = make_uint4(0, 0, 0, 0);
        uint4* o = (uint4*)rowout;
        for (int e = t; e < 26 * KPRIME / 8; e += 256) o[e] = z;
        return;
    }
    int b = p - 1, y = yq - 1;
    {
        uint4 z = make_uint4(0, 0, 0, 0);
        uint4* o0 = (uint4*)rowout;
        uint4* o1 = (uint4*)(rowout + (size_t)25 * KPRIME);
        for (int e = t; e < KPRIME / 8; e += 256) { o0[e] = z; o1[e] = z; }
    }
    for (int pass = 0; pass < 2; ++pass) {
        const float* in = pass ? det : src;
        for (int e = t; e < 256 * 24; e += 256) {
            int ch = e / 24, x = e - ch * 24;
            s[ch][x] = in[((size_t)b * 256 + ch) * 576 + y * 24 + x];
        }
        __syncthreads();
        int cb = pass * 256;
        for (int x = 0; x < 24; ++x) {
            float v = s[t][x];
            __nv_bfloat16 h = __float2bfloat16(v);
            __nv_bfloat16 l = __float2bfloat16(v - __bfloat162float(h));
            __nv_bfloat16* o = rowout + (size_t)(x + 1) * KPRIME;
            o[cb + t] = h;
            o[512 + cb + t] = l;
            o[1024 + cb + t] = h;
        }
        __syncthreads();
    }
}

// ---------------- conv1: 128x128 CTA tile, mma.sync bf16 ----------------
// K-chunk 64: stage = A 16KB + B 16KB = 32KB; 3 stages = 96KB -> 2 CTA/SM.
#define CONV1_SMEM (3 * 32768)

__global__ __launch_bounds__(256, 2) void conv1_mma() {
    extern __shared__ __align__(1024) char smem_raw[];
    const uint32_t sbase = smem_u32(smem_raw);

    const int t = threadIdx.x;
    const int l = t & 31;
    const int w = t >> 5;
    const int m0 = blockIdx.y * 128;        // M tile
    const int nbase = blockIdx.x * 128;     // N half

    // ---- staging precompute: thread t -> row t&127, k-half t>>7, 4 granules ----
    const int srow = t & 127;
    const int shalf = t >> 7;
    uint32_t sdst[4];
#pragma unroll
    for (int g = 0; g < 4; g++) {
        int ch = shalf * 4 + g;                              // 16B chunk in 128B row
        sdst[g] = (uint32_t)srow * 128u + (uint32_t)((ch ^ (srow & 7)) * 16);
    }
    const size_t arow_noshift = (size_t)(NPLANE + m0 + srow);

    // ---- compute-side precompute ----
    const int wm = (w >> 2) * 64;            // warp M offset (0/64)
    const int wn = (w & 3) * 32;             // warp N offset (0/32/64/96)
    const int rsw = l & 7;                   // swizzle key (row & 7)
    uint32_t aRow[4], bRow[4];
#pragma unroll
    for (int mi = 0; mi < 4; mi++) aRow[mi] = (uint32_t)(wm + mi * 16 + (l & 15)) * 128u;
#pragma unroll
    for (int ni = 0; ni < 4; ni++) bRow[ni] = (uint32_t)(wn + ni * 8 + (l & 7)) * 128u;
    const uint32_t aHi = (uint32_t)(l >> 4);         // 0/1
    const uint32_t bHi = (uint32_t)((l >> 3) & 1);   // 0/1

    float acc[4][4][4];
#pragma unroll
    for (int mi = 0; mi < 4; mi++)
#pragma unroll
        for (int ni = 0; ni < 4; ni++)
#pragma unroll
            for (int r = 0; r < 4; r++) acc[mi][ni][r] = 0.f;

    // ---- chunk load issue (chunk = 64 k-elements = 128B per row) ----
    auto issue = [&](int c) {
        const int tap = c / 24;
        const int kc = (c - tap * 24) * 64;
        const int ty = tap / 3, tx = tap - ty * 3;
        const int shift = (ty - 1) * 26 + (tx - 1);
        const uint32_t As = sbase + (uint32_t)(c % 3) * 32768u;
        const uint32_t Bs = As + 16384u;
        const __nv_bfloat16* asrc = g_xs + (arow_noshift + shift) * KPRIME + kc + shalf * 32;
        const __nv_bfloat16* bsrc = g_wb + ((size_t)(tap * 256 + nbase + srow)) * KPRIME
                                  + kc + shalf * 32;
#pragma unroll
        for (int g = 0; g < 4; g++) {
            CP_ASYNC16(As + sdst[g], asrc + g * 8);
            CP_ASYNC16(Bs + sdst[g], bsrc + g * 8);
        }
    };

    auto compute = [&](int c) {
        const uint32_t As = sbase + (uint32_t)(c % 3) * 32768u;
        const uint32_t Bs = As + 16384u;
#pragma unroll
        for (int ks = 0; ks < 4; ks++) {
            uint32_t a[4][4], b[4][2];
            const uint32_t ca = (uint32_t)(ks * 2) + aHi;
            const uint32_t cb = (uint32_t)(ks * 2) + bHi;
            const uint32_t aoff = ((ca ^ rsw) << 4);
            const uint32_t boff = ((cb ^ rsw) << 4);
#pragma unroll
            for (int mi = 0; mi < 4; mi++) ldsm_x4(a[mi], As + aRow[mi] + aoff);
#pragma unroll
            for (int ni = 0; ni < 4; ni++) ldsm_x2(b[ni], Bs + bRow[ni] + boff);
#pragma unroll
            for (int mi = 0; mi < 4; mi++)
#pragma unroll
                for (int ni = 0; ni < 4; ni++)
                    mma_bf16(acc[mi][ni], a[mi], b[ni]);
        }
    };

    // ---- 3-stage pipeline, ONE sync per chunk ----
    issue(0); CP_COMMIT();
    issue(1); CP_COMMIT();
    for (int c = 0; c < N_CHUNKS; ++c) {
        if (c < N_CHUNKS - 1) { CP_WAIT(1); } else { CP_WAIT(0); }
        __syncthreads();
        if (c + 2 < N_CHUNKS) { issue(c + 2); CP_COMMIT(); }
        compute(c);
    }

    // ---- epilogue: BN + ReLU, drop padded rows, write g_x1 (NCHW) ----
    bool mvalid[8];
    float* mptr[8];
#pragma unroll
    for (int mi = 0; mi < 4; mi++)
#pragma unroll
        for (int h = 0; h < 2; h++) {
            int i = mi * 2 + h;
            int mg = m0 + wm + mi * 16 + (l >> 2) + h * 8;
            int plane = mg / 676;
            int pos = mg - plane * 676;
            int yq = pos / 26, xq = pos - yq * 26;
            mvalid[i] = (yq >= 1 && yq <= 24 && xq >= 1 && xq <= 24);
            mptr[i] = g_x1 + (size_t)plane * 147456 + (yq - 1) * 24 + (xq - 1);
        }
#pragma unroll
    for (int ni = 0; ni < 4; ni++) {
        int n0 = nbase + wn + ni * 8 + (l & 3) * 2;
        float sc0 = g_scale[n0], sh0 = g_shift[n0];
        float sc1 = g_scale[n0 + 1], sh1 = g_shift[n0 + 1];
#pragma unroll
        for (int mi = 0; mi < 4; mi++)
#pragma unroll
            for (int h = 0; h < 2; h++) {
                int i = mi * 2 + h;
                if (!mvalid[i]) continue;
                float v0 = fmaf(acc[mi][ni][h * 2 + 0], sc0, sh0);
                float v1 = fmaf(acc[mi][ni][h * 2 + 1], sc1, sh1);
                mptr[i][(size_t)n0 * 576] = fmaxf(v0, 0.f);
                mptr[i][(size_t)(n0 + 1) * 576] = fmaxf(v1, 0.f);
            }
    }
}

// ---------------- conv2 (1x1, 256->25) + bias + softmax ----------------
__global__ __launch_bounds__(128) void conv2_kernel(const float* __restrict__ w2,
                                                    const float* __restrict__ b2) {
    __shared__ float As[16][128];
    __shared__ float Bs[16][25];
    __shared__ float b2s[25];

    const int t = threadIdx.x;
    const int m = blockIdx.x * 128 + t;
    const int b = m / 576;
    const int pos = m - b * 576;
    const float* xp = g_x1 + (size_t)b * 147456 + pos;

    if (t < 25) b2s[t] = b2[t];

    float acc[25];
#pragma unroll
    for (int n = 0; n < 25; n++) acc[n] = 0.f;

    for (int kc = 0; kc < 256; kc += 16) {
#pragma unroll
        for (int kk = 0; kk < 16; kk++) As[kk][t] = xp[(size_t)(kc + kk) * 576];
        for (int e = t; e < 400; e += 128) {
            int k = e / 25;
            int n = e - k * 25;
            Bs[k][n] = w2[n * 256 + kc + k];
        }
        __syncthreads();
#pragma unroll
        for (int kk = 0; kk < 16; kk++) {
            float a = As[kk][t];
#pragma unroll
            for (int n = 0; n < 25; n++) acc[n] = fmaf(a, Bs[kk][n], acc[n]);
        }
        __syncthreads();
    }

    float mx = -1e30f;
#pragma unroll
    for (int n = 0; n < 25; n++) { acc[n] += b2s[n]; mx = fmaxf(mx, acc[n]); }
    float sum = 0.f;
#pragma unroll
    for (int n = 0; n < 25; n++) { acc[n] = __expf(acc[n] - mx); sum += acc[n]; }
    float inv = 1.f / sum;

    float* kp = g_kmap + (size_t)b * 14400 + pos;
#pragma unroll
    for (int n = 0; n < 25; n++) kp[(size_t)n * 576] = acc[n] * inv;
}

// ---------------- 25-tap propagation (channel-split grid) ----------------
// block = (batch, 8-row group, 32-channel slice); 3072 blocks of 192 threads.
#define CSPLIT 8
#define CPB    32     // channels per block

__global__ __launch_bounds__(192) void prop_kernel(const float* __restrict__ src,
                                                   float* __restrict__ out) {
    __shared__ float patch[2][336];

    const int t = threadIdx.x;
    const int blk = blockIdx.x;
    const int cs = blk & (CSPLIT - 1);
    const int brg = blk >> 3;
    const int b = brg / 3;
    const int rg = brg - b * 3;
    const int pos0 = rg * 192;
    const int y0 = rg * 8;
    const int c0 = cs * CPB;

    float pr[25];
    const float* kp = g_kmap + (size_t)b * 14400 + pos0 + t;
#pragma unroll
    for (int n = 0; n < 25; n++) pr[n] = kp[(size_t)n * 576];

    int off[2];
    bool val[2];
#pragma unroll
    for (int i = 0; i < 2; i++) {
        int e = t + i * 192;
        int ry = e / 28;
        int rx = e - ry * 28;
        int iy = y0 - 2 + ry;
        int ix = rx - 2;
        val[i] = (e < 336) && iy >= 0 && iy < 24 && ix >= 0 && ix < 24;
        off[i] = val[i] ? iy * 24 + ix : 0;
    }

    const float* sb = src + (size_t)b * 147456 + (size_t)c0 * 576;
    const int py = t / 24 + 2;
    const int px = t - (t / 24) * 24 + 2;
    const int pcenter = py * 28 + px;
    float* ob = out + (size_t)b * 147456 + (size_t)c0 * 576 + pos0 + t;

#pragma unroll
    for (int i = 0; i < 2; i++) {
        int e = t + i * 192;
        if (e < 336) patch[0][e] = val[i] ? sb[off[i]] : 0.f;
    }
    __syncthreads();

    for (int c = 0; c < CPB; ++c) {
        float nv[2];
        if (c + 1 < CPB) {
#pragma unroll
            for (int i = 0; i < 2; i++)
                nv[i] = val[i] ? sb[(size_t)(c + 1) * 576 + off[i]] : 0.f;
        }
        const float* pc = &patch[c & 1][0];
        float sum = 0.f;
#pragma unroll
        for (int o = 0; o < 25; o++) {
            int ddy = o / 5 - 2;
            int ddx = o - (o / 5) * 5 - 2;
            sum = fmaf(pc[pcenter + ddy * 28 + ddx], pr[o], sum);
        }
        ob[(size_t)c * 576] = sum;

        if (c + 1 < CPB) {
#pragma unroll
            for (int i = 0; i < 2; i++) {
                int e = t + i * 192;
                if (e < 336) patch[(c + 1) & 1][e] = nv[i];
            }
        }
        __syncthreads();
    }
}

// ---------------- launcher ----------------
extern "C" void kernel_launch(void* const* d_in, const int* in_sizes, int n_in,
                              void* d_out, int out_size) {
    const float* src = (const float*)d_in[0];
    const float* det = (const float*)d_in[1];
    const float* w1  = (const float*)d_in[2];
    const float* b1  = (const float*)d_in[3];
    const float* gam = (const float*)d_in[4];
    const float* bet = (const float*)d_in[5];
    const float* mu  = (const float*)d_in[6];
    const float* var = (const float*)d_in[7];
    const float* w2  = (const float*)d_in[8];
    const float* b2  = (const float*)d_in[9];
    float* out = (float*)d_out;

    cudaFuncSetAttribute(conv1_mma, cudaFuncAttributeMaxDynamicSharedMemorySize, CONV1_SMEM);

    snprep_kernel<<<1, 256>>>(b1, gam, bet, mu, var);
    wprep_kernel<<<(9 * 256 * KPRIME + 255) / 256, 256>>>(w1);
    xprep_kernel<<<130 * 26, 256>>>(src, det);

    dim3 g1(2, 676);                        // x = N half, y = M tile
    conv1_mma<<<g1, 256, CONV1_SMEM>>>();

    conv2_kernel<<<576, 128>>>(w2, b2);
    prop_kernel<<<128 * 3 * CSPLIT, 192>>>(src, out);
}

// round 5
// speedup vs baseline: 1.8501x; 1.5873x over previous
#include <cuda_runtime.h>
#include <cuda_fp16.h>
#include <cstdint>
#include <math.h>

// ============================================================================
// conv1 via mma.sync fp16 (HMMA), fp32 emulated with fp16x2 split:
//   A k-layout [Ah|Al], B k-layout [Bh|Bh]  => computes A*Bh, err ~ 2^-11.
//   K' = 2*4608 = 9216. Padded-plane M: 26x26=676/plane, 130 planes.
// CTA tile 128M x 256N, 8 warps (2x4), warp 64x64, K-chunk 64, 3-stage cp.async.
// ============================================================================

#define NPLANE   676
#define KPRIME   1024              // per-tap k': Ah(512)|Al(512)
#define N_CHUNKS 144               // 9 taps * 16 chunks of 64
#define STAGE_B  49152             // A 16KB + B 32KB
#define CONV1_SMEM (3 * STAGE_B)

// ---------------- static device scratch ----------------
__device__ __half g_xs[130 * NPLANE * KPRIME];   // padded NHWC fp16x2 (~180MB)
__device__ __half g_wb[9 * 256 * KPRIME];        // weights [tap][n][k']
__device__ float g_scale[256];
__device__ float g_shift[256];
__device__ float g_x1[128 * 256 * 576];          // conv1 out, NCHW
__device__ float g_kmap[128 * 25 * 576];         // softmax maps

// ---------------- PTX helpers ----------------
__device__ __forceinline__ uint32_t smem_u32(const void* p) {
    uint32_t a;
    asm("{ .reg .u64 t; cvta.to.shared.u64 t, %1; cvt.u32.u64 %0, t; }" : "=r"(a) : "l"(p));
    return a;
}
#define CP_ASYNC16(dst, src) \
    asm volatile("cp.async.cg.shared.global [%0], [%1], 16;" :: "r"(dst), "l"(src) : "memory")
#define CP_COMMIT() asm volatile("cp.async.commit_group;" ::: "memory")
#define CP_WAIT(n)  asm volatile("cp.async.wait_group %0;" :: "n"(n) : "memory")

__device__ __forceinline__ void ldsm_x4(uint32_t* r, uint32_t addr) {
    asm volatile("ldmatrix.sync.aligned.m8n8.x4.shared.b16 {%0,%1,%2,%3}, [%4];"
                 : "=r"(r[0]), "=r"(r[1]), "=r"(r[2]), "=r"(r[3]) : "r"(addr));
}
__device__ __forceinline__ void mma_f16(float* c, const uint32_t* a, uint32_t b0, uint32_t b1) {
    asm volatile("mma.sync.aligned.m16n8k16.row.col.f32.f16.f16.f32 "
                 "{%0,%1,%2,%3}, {%4,%5,%6,%7}, {%8,%9}, {%0,%1,%2,%3};"
                 : "+f"(c[0]), "+f"(c[1]), "+f"(c[2]), "+f"(c[3])
                 : "r"(a[0]), "r"(a[1]), "r"(a[2]), "r"(a[3]), "r"(b0), "r"(b1));
}

// ---------------- prep: BN scale/shift fold ----------------
__global__ void snprep_kernel(const float* __restrict__ b1, const float* __restrict__ gam,
                              const float* __restrict__ bet, const float* __restrict__ mu,
                              const float* __restrict__ var) {
    int i = threadIdx.x;
    float inv = gam[i] * rsqrtf(var[i] + 1e-5f);
    g_scale[i] = inv;
    g_shift[i] = bet[i] + (b1[i] - mu[i]) * inv;
}

// ---------------- prep: weights -> fp16 [tap][n][Bh|Bh] ----------------
__global__ void wprep_kernel(const float* __restrict__ w1) {
    int idx = blockIdx.x * 256 + threadIdx.x;
    if (idx >= 9 * 256 * KPRIME) return;
    int kp = idx & 1023;
    int n = (idx >> 10) & 255;
    int tap = idx >> 18;
    int c = kp & 511;                    // both halves use the same channel
    float v = w1[((size_t)n * 512 + c) * 9 + tap];
    g_wb[idx] = __float2half(v);         // Bh duplicated across both halves
}

// ---------------- prep: inputs -> padded NHWC fp16 [Ah|Al] ----------------
__global__ __launch_bounds__(256) void xprep_kernel(const float* __restrict__ src,
                                                    const float* __restrict__ det) {
    __shared__ float s[256][25];
    int blk = blockIdx.x;
    int p = blk / 26, yq = blk % 26;
    int t = threadIdx.x;
    __half* rowout = g_xs + (size_t)(p * NPLANE + yq * 26) * KPRIME;
    bool interior = (p >= 1 && p <= 128 && yq >= 1 && yq <= 24);
    if (!interior) {
        uint4 z = make_uint4(0, 0, 0, 0);
        uint4* o = (uint4*)rowout;
        for (int e = t; e < 26 * KPRIME / 8; e += 256) o[e] = z;
        return;
    }
    int b = p - 1, y = yq - 1;
    {
        uint4 z = make_uint4(0, 0, 0, 0);
        uint4* o0 = (uint4*)rowout;
        uint4* o1 = (uint4*)(rowout + (size_t)25 * KPRIME);
        for (int e = t; e < KPRIME / 8; e += 256) { o0[e] = z; o1[e] = z; }
    }
    for (int pass = 0; pass < 2; ++pass) {
        const float* in = pass ? det : src;
        for (int e = t; e < 256 * 24; e += 256) {
            int ch = e / 24, x = e - ch * 24;
            s[ch][x] = in[((size_t)b * 256 + ch) * 576 + y * 24 + x];
        }
        __syncthreads();
        int cb = pass * 256;
        for (int x = 0; x < 24; ++x) {
            float v = s[t][x];
            __half h = __float2half(v);
            __half l = __float2half(v - __half2float(h));
            __half* o = rowout + (size_t)(x + 1) * KPRIME;
            o[cb + t] = h;
            o[512 + cb + t] = l;
        }
        __syncthreads();
    }
}

// ---------------- conv1: 128x256 CTA tile, warp 64x64, mma.sync fp16 ----------
__global__ __launch_bounds__(256) void conv1_mma() {
    extern __shared__ __align__(1024) char smem_raw[];
    const uint32_t sbase = smem_u32(smem_raw);

    const int t = threadIdx.x;
    const int l = t & 31;
    const int w = t >> 5;
    const int m0 = blockIdx.x * 128;

    // ---- staging precompute ----
    // A: thread t -> row t>>1 (128 rows), half t&1, 4x16B
    const int arow = t >> 1;
    const int ahalf = t & 1;
    uint32_t sdstA[4];
#pragma unroll
    for (int g = 0; g < 4; g++) {
        int ch = ahalf * 4 + g;
        sdstA[g] = (uint32_t)arow * 128u + (uint32_t)((ch ^ (arow & 7)) * 16);
    }
    // B: thread t -> row t (256 rows), 8x16B
    uint32_t sdstB[8];
#pragma unroll
    for (int g = 0; g < 8; g++)
        sdstB[g] = 16384u + (uint32_t)t * 128u + (uint32_t)((g ^ (t & 7)) * 16);
    const size_t arow_noshift = (size_t)(NPLANE + m0 + arow);

    // ---- compute-side precompute ----
    const int wm = (w >> 2) * 64;            // warp M (0/64)
    const int wn = (w & 3) * 64;             // warp N (0/64/128/192)
    const uint32_t rsw = (uint32_t)(l & 7);
    const uint32_t kHi = (uint32_t)(l >> 4);
    uint32_t aRow[4], bRow[4];
#pragma unroll
    for (int mi = 0; mi < 4; mi++) aRow[mi] = (uint32_t)(wm + mi * 16 + (l & 15)) * 128u;
#pragma unroll
    for (int gi = 0; gi < 4; gi++) bRow[gi] = 16384u + (uint32_t)(wn + gi * 16 + (l & 15)) * 128u;

    float acc[4][8][4];
#pragma unroll
    for (int mi = 0; mi < 4; mi++)
#pragma unroll
        for (int ni = 0; ni < 8; ni++)
#pragma unroll
            for (int r = 0; r < 4; r++) acc[mi][ni][r] = 0.f;

    auto issue = [&](int c) {
        const int tap = c >> 4;
        const int kc = (c & 15) * 64;
        const int ty = tap / 3, tx = tap - ty * 3;
        const int shift = (ty - 1) * 26 + (tx - 1);
        const uint32_t St = sbase + (uint32_t)(c % 3) * STAGE_B;
        const __half* asrc = g_xs + (arow_noshift + shift) * KPRIME + kc + ahalf * 32;
        const __half* bsrc = g_wb + ((size_t)(tap * 256 + t)) * KPRIME + kc;
#pragma unroll
        for (int g = 0; g < 4; g++) CP_ASYNC16(St + sdstA[g], asrc + g * 8);
#pragma unroll
        for (int g = 0; g < 8; g++) CP_ASYNC16(St + sdstB[g], bsrc + g * 8);
    };

    auto compute = [&](int c) {
        const uint32_t St = sbase + (uint32_t)(c % 3) * STAGE_B;
#pragma unroll
        for (int ks = 0; ks < 4; ks++) {
            const uint32_t off = (((uint32_t)(ks * 2) + kHi) ^ rsw) << 4;
            uint32_t a[4][4], b[4][4];
#pragma unroll
            for (int mi = 0; mi < 4; mi++) ldsm_x4(a[mi], St + aRow[mi] + off);
#pragma unroll
            for (int gi = 0; gi < 4; gi++) ldsm_x4(b[gi], St + bRow[gi] + off);
#pragma unroll
            for (int mi = 0; mi < 4; mi++)
#pragma unroll
                for (int gi = 0; gi < 4; gi++) {
                    mma_f16(acc[mi][gi * 2 + 0], a[mi], b[gi][0], b[gi][2]);
                    mma_f16(acc[mi][gi * 2 + 1], a[mi], b[gi][1], b[gi][3]);
                }
        }
    };

    issue(0); CP_COMMIT();
    issue(1); CP_COMMIT();
    for (int c = 0; c < N_CHUNKS; ++c) {
        if (c < N_CHUNKS - 1) { CP_WAIT(1); } else { CP_WAIT(0); }
        __syncthreads();
        if (c + 2 < N_CHUNKS) { issue(c + 2); CP_COMMIT(); }
        compute(c);
    }

    // ---- epilogue: BN + ReLU, drop padded rows, write g_x1 (NCHW) ----
    bool mvalid[8];
    float* mptr[8];
#pragma unroll
    for (int mi = 0; mi < 4; mi++)
#pragma unroll
        for (int h = 0; h < 2; h++) {
            int i = mi * 2 + h;
            int mg = m0 + wm + mi * 16 + (l >> 2) + h * 8;
            int plane = mg / 676;
            int pos = mg - plane * 676;
            int yq = pos / 26, xq = pos - yq * 26;
            mvalid[i] = (yq >= 1 && yq <= 24 && xq >= 1 && xq <= 24);
            mptr[i] = g_x1 + (size_t)plane * 147456 + (yq - 1) * 24 + (xq - 1);
        }
#pragma unroll
    for (int ni = 0; ni < 8; ni++) {
        int n0 = wn + (ni >> 1) * 16 + (ni & 1) * 8 + (l & 3) * 2;
        float sc0 = g_scale[n0], sh0 = g_shift[n0];
        float sc1 = g_scale[n0 + 1], sh1 = g_shift[n0 + 1];
#pragma unroll
        for (int mi = 0; mi < 4; mi++)
#pragma unroll
            for (int h = 0; h < 2; h++) {
                int i = mi * 2 + h;
                if (!mvalid[i]) continue;
                float v0 = fmaf(acc[mi][ni][h * 2 + 0], sc0, sh0);
                float v1 = fmaf(acc[mi][ni][h * 2 + 1], sc1, sh1);
                mptr[i][(size_t)n0 * 576] = fmaxf(v0, 0.f);
                mptr[i][(size_t)(n0 + 1) * 576] = fmaxf(v1, 0.f);
            }
    }
}

// ---------------- conv2 (1x1, 256->25) + bias + softmax ----------------
__global__ __launch_bounds__(128) void conv2_kernel(const float* __restrict__ w2,
                                                    const float* __restrict__ b2) {
    __shared__ float As[16][128];
    __shared__ float Bs[16][25];
    __shared__ float b2s[25];

    const int t = threadIdx.x;
    const int m = blockIdx.x * 128 + t;
    const int b = m / 576;
    const int pos = m - b * 576;
    const float* xp = g_x1 + (size_t)b * 147456 + pos;

    if (t < 25) b2s[t] = b2[t];

    float acc[25];
#pragma unroll
    for (int n = 0; n < 25; n++) acc[n] = 0.f;

    for (int kc = 0; kc < 256; kc += 16) {
#pragma unroll
        for (int kk = 0; kk < 16; kk++) As[kk][t] = xp[(size_t)(kc + kk) * 576];
        for (int e = t; e < 400; e += 128) {
            int k = e / 25;
            int n = e - k * 25;
            Bs[k][n] = w2[n * 256 + kc + k];
        }
        __syncthreads();
#pragma unroll
        for (int kk = 0; kk < 16; kk++) {
            float a = As[kk][t];
#pragma unroll
            for (int n = 0; n < 25; n++) acc[n] = fmaf(a, Bs[kk][n], acc[n]);
        }
        __syncthreads();
    }

    float mx = -1e30f;
#pragma unroll
    for (int n = 0; n < 25; n++) { acc[n] += b2s[n]; mx = fmaxf(mx, acc[n]); }
    float sum = 0.f;
#pragma unroll
    for (int n = 0; n < 25; n++) { acc[n] = __expf(acc[n] - mx); sum += acc[n]; }
    float inv = 1.f / sum;

    float* kp = g_kmap + (size_t)b * 14400 + pos;
#pragma unroll
    for (int n = 0; n < 25; n++) kp[(size_t)n * 576] = acc[n] * inv;
}

// ---------------- 25-tap propagation (channel-split grid) ----------------
#define CSPLIT 8
#define CPB    32

__global__ __launch_bounds__(192) void prop_kernel(const float* __restrict__ src,
                                                   float* __restrict__ out) {
    __shared__ float patch[2][336];

    const int t = threadIdx.x;
    const int blk = blockIdx.x;
    const int cs = blk & (CSPLIT - 1);
    const int brg = blk >> 3;
    const int b = brg / 3;
    const int rg = brg - b * 3;
    const int pos0 = rg * 192;
    const int y0 = rg * 8;
    const int c0 = cs * CPB;

    float pr[25];
    const float* kp = g_kmap + (size_t)b * 14400 + pos0 + t;
#pragma unroll
    for (int n = 0; n < 25; n++) pr[n] = kp[(size_t)n * 576];

    int off[2];
    bool val[2];
#pragma unroll
    for (int i = 0; i < 2; i++) {
        int e = t + i * 192;
        int ry = e / 28;
        int rx = e - ry * 28;
        int iy = y0 - 2 + ry;
        int ix = rx - 2;
        val[i] = (e < 336) && iy >= 0 && iy < 24 && ix >= 0 && ix < 24;
        off[i] = val[i] ? iy * 24 + ix : 0;
    }

    const float* sb = src + (size_t)b * 147456 + (size_t)c0 * 576;
    const int py = t / 24 + 2;
    const int px = t - (t / 24) * 24 + 2;
    const int pcenter = py * 28 + px;
    float* ob = out + (size_t)b * 147456 + (size_t)c0 * 576 + pos0 + t;

#pragma unroll
    for (int i = 0; i < 2; i++) {
        int e = t + i * 192;
        if (e < 336) patch[0][e] = val[i] ? sb[off[i]] : 0.f;
    }
    __syncthreads();

    for (int c = 0; c < CPB; ++c) {
        float nv[2];
        if (c + 1 < CPB) {
#pragma unroll
            for (int i = 0; i < 2; i++)
                nv[i] = val[i] ? sb[(size_t)(c + 1) * 576 + off[i]] : 0.f;
        }
        const float* pc = &patch[c & 1][0];
        float sum = 0.f;
#pragma unroll
        for (int o = 0; o < 25; o++) {
            int ddy = o / 5 - 2;
            int ddx = o - (o / 5) * 5 - 2;
            sum = fmaf(pc[pcenter + ddy * 28 + ddx], pr[o], sum);
        }
        ob[(size_t)c * 576] = sum;

        if (c + 1 < CPB) {
#pragma unroll
            for (int i = 0; i < 2; i++) {
                int e = t + i * 192;
                if (e < 336) patch[(c + 1) & 1][e] = nv[i];
            }
        }
        __syncthreads();
    }
}

// ---------------- launcher ----------------
extern "C" void kernel_launch(void* const* d_in, const int* in_sizes, int n_in,
                              void* d_out, int out_size) {
    const float* src = (const float*)d_in[0];
    const float* det = (const float*)d_in[1];
    const float* w1  = (const float*)d_in[2];
    const float* b1  = (const float*)d_in[3];
    const float* gam = (const float*)d_in[4];
    const float* bet = (const float*)d_in[5];
    const float* mu  = (const float*)d_in[6];
    const float* var = (const float*)d_in[7];
    const float* w2  = (const float*)d_in[8];
    const float* b2  = (const float*)d_in[9];
    float* out = (float*)d_out;

    cudaFuncSetAttribute(conv1_mma, cudaFuncAttributeMaxDynamicSharedMemorySize, CONV1_SMEM);

    snprep_kernel<<<1, 256>>>(b1, gam, bet, mu, var);
    wprep_kernel<<<(9 * 256 * KPRIME + 255) / 256, 256>>>(w1);
    xprep_kernel<<<130 * 26, 256>>>(src, det);

    conv1_mma<<<676, 256, CONV1_SMEM>>>();

    conv2_kernel<<<576, 128>>>(w2, b2);
    prop_kernel<<<128 * 3 * CSPLIT, 192>>>(src, out);
}

// round 6
// speedup vs baseline: 4.0282x; 2.1773x over previous
#include <cuda_runtime.h>
#include <cuda_fp16.h>
#include <cstdint>
#include <math.h>

// ============================================================================
// conv1 via mma.sync fp16 (HMMA), pure fp16 inputs (err ~2^-11 rel, measured
// budget ~2.5e-4 << 1e-3). K' = 4608 (9 taps * 512).
// Padded-plane M: 26x26=676/plane, 130 planes (guards).
// CTA tile 128M x 256N, 512 thr / 16 warps (4Mx4N), warp 32x64, K-chunk 64,
// 3-stage cp.async (144KB smem).
// ============================================================================

#define NPLANE   676
#define KPRIME   512               // per-tap k' (pure fp16)
#define N_CHUNKS 72                // 9 taps * 8 chunks of 64
#define STAGE_B  49152             // A 16KB + B 32KB
#define CONV1_SMEM (3 * STAGE_B)

// ---------------- static device scratch ----------------
__device__ __half g_xs[130 * NPLANE * KPRIME];   // padded NHWC fp16 (~90MB)
__device__ __half g_wb[9 * 256 * KPRIME];        // weights [tap][n][k]
__device__ float g_scale[256];
__device__ float g_shift[256];
__device__ float g_x1[128 * 256 * 576];          // conv1 out, NCHW
__device__ float g_kmap[128 * 25 * 576];         // softmax maps

// ---------------- PTX helpers ----------------
__device__ __forceinline__ uint32_t smem_u32(const void* p) {
    uint32_t a;
    asm("{ .reg .u64 t; cvta.to.shared.u64 t, %1; cvt.u32.u64 %0, t; }" : "=r"(a) : "l"(p));
    return a;
}
#define CP_ASYNC16(dst, src) \
    asm volatile("cp.async.cg.shared.global [%0], [%1], 16;" :: "r"(dst), "l"(src) : "memory")
#define CP_COMMIT() asm volatile("cp.async.commit_group;" ::: "memory")
#define CP_WAIT(n)  asm volatile("cp.async.wait_group %0;" :: "n"(n) : "memory")

__device__ __forceinline__ void ldsm_x4(uint32_t* r, uint32_t addr) {
    asm volatile("ldmatrix.sync.aligned.m8n8.x4.shared.b16 {%0,%1,%2,%3}, [%4];"
                 : "=r"(r[0]), "=r"(r[1]), "=r"(r[2]), "=r"(r[3]) : "r"(addr));
}
__device__ __forceinline__ void mma_f16(float* c, const uint32_t* a, uint32_t b0, uint32_t b1) {
    asm volatile("mma.sync.aligned.m16n8k16.row.col.f32.f16.f16.f32 "
                 "{%0,%1,%2,%3}, {%4,%5,%6,%7}, {%8,%9}, {%0,%1,%2,%3};"
                 : "+f"(c[0]), "+f"(c[1]), "+f"(c[2]), "+f"(c[3])
                 : "r"(a[0]), "r"(a[1]), "r"(a[2]), "r"(a[3]), "r"(b0), "r"(b1));
}

// ---------------- prep: BN scale/shift fold ----------------
__global__ void snprep_kernel(const float* __restrict__ b1, const float* __restrict__ gam,
                              const float* __restrict__ bet, const float* __restrict__ mu,
                              const float* __restrict__ var) {
    int i = threadIdx.x;
    float inv = gam[i] * rsqrtf(var[i] + 1e-5f);
    g_scale[i] = inv;
    g_shift[i] = bet[i] + (b1[i] - mu[i]) * inv;
}

// ---------------- prep: weights -> fp16 [tap][n][k] ----------------
__global__ void wprep_kernel(const float* __restrict__ w1) {
    int idx = blockIdx.x * 256 + threadIdx.x;
    if (idx >= 9 * 256 * KPRIME) return;
    int kp = idx & 511;
    int n = (idx >> 9) & 255;
    int tap = idx >> 17;
    g_wb[idx] = __float2half(w1[((size_t)n * 512 + kp) * 9 + tap]);
}

// ---------------- prep: inputs -> padded NHWC fp16 ----------------
__global__ __launch_bounds__(256) void xprep_kernel(const float* __restrict__ src,
                                                    const float* __restrict__ det) {
    __shared__ float s[256][25];
    int blk = blockIdx.x;
    int p = blk / 26, yq = blk % 26;
    int t = threadIdx.x;
    __half* rowout = g_xs + (size_t)(p * NPLANE + yq * 26) * KPRIME;
    bool interior = (p >= 1 && p <= 128 && yq >= 1 && yq <= 24);
    if (!interior) {
        uint4 z = make_uint4(0, 0, 0, 0);
        uint4* o = (uint4*)rowout;
        for (int e = t; e < 26 * KPRIME / 8; e += 256) o[e] = z;
        return;
    }
    int b = p - 1, y = yq - 1;
    {
        uint4 z = make_uint4(0, 0, 0, 0);
        uint4* o0 = (uint4*)rowout;
        uint4* o1 = (uint4*)(rowout + (size_t)25 * KPRIME);
        for (int e = t; e < KPRIME / 8; e += 256) { o0[e] = z; o1[e] = z; }
    }
    for (int pass = 0; pass < 2; ++pass) {
        const float* in = pass ? det : src;
        for (int e = t; e < 256 * 24; e += 256) {
            int ch = e / 24, x = e - ch * 24;
            s[ch][x] = in[((size_t)b * 256 + ch) * 576 + y * 24 + x];
        }
        __syncthreads();
        int cb = pass * 256;
        for (int x = 0; x < 24; ++x) {
            __half* o = rowout + (size_t)(x + 1) * KPRIME;
            o[cb + t] = __float2half(s[t][x]);
        }
        __syncthreads();
    }
}

// ---------------- conv1: 128x256 CTA, 512 thr, warp 32x64, mma.sync fp16 ------
__global__ __launch_bounds__(512) void conv1_mma() {
    extern __shared__ __align__(1024) char smem_raw[];
    const uint32_t sbase = smem_u32(smem_raw);

    const int t = threadIdx.x;
    const int l = t & 31;
    const int w = t >> 5;                   // 0..15
    const int m0 = blockIdx.x * 128;

    // ---- staging precompute ----
    // A: 16KB/stage, 1024 16B-chunks, 2 per thread. row = t>>2, quarter q=t&3.
    const int arow = t >> 2;
    const int aq = t & 3;
    uint32_t sdstA[2];
#pragma unroll
    for (int g = 0; g < 2; g++) {
        int ch = aq * 2 + g;
        sdstA[g] = (uint32_t)arow * 128u + (uint32_t)((ch ^ (arow & 7)) * 16);
    }
    // B: 32KB/stage, row = t>>1, half bh=t&1, 4 chunks.
    const int brow = t >> 1;
    const int bh = t & 1;
    uint32_t sdstB[4];
#pragma unroll
    for (int g = 0; g < 4; g++) {
        int ch = bh * 4 + g;
        sdstB[g] = 16384u + (uint32_t)brow * 128u + (uint32_t)((ch ^ (brow & 7)) * 16);
    }
    const size_t arow_noshift = (size_t)(NPLANE + m0 + arow);

    // ---- compute-side precompute ----
    const int wm = (w >> 2) * 32;            // warp M (0/32/64/96)
    const int wn = (w & 3) * 64;             // warp N (0/64/128/192)
    const uint32_t rsw = (uint32_t)(l & 7);
    const uint32_t kHi = (uint32_t)(l >> 4);
    uint32_t aRow[2], bRow[4];
#pragma unroll
    for (int mi = 0; mi < 2; mi++) aRow[mi] = (uint32_t)(wm + mi * 16 + (l & 15)) * 128u;
#pragma unroll
    for (int gi = 0; gi < 4; gi++) bRow[gi] = 16384u + (uint32_t)(wn + gi * 16 + (l & 15)) * 128u;

    float acc[2][8][4];
#pragma unroll
    for (int mi = 0; mi < 2; mi++)
#pragma unroll
        for (int ni = 0; ni < 8; ni++)
#pragma unroll
            for (int r = 0; r < 4; r++) acc[mi][ni][r] = 0.f;

    auto issue = [&](int c) {
        const int tap = c >> 3;                 // 8 chunks per tap
        const int kc = (c & 7) * 64;
        const int ty = tap / 3, tx = tap - ty * 3;
        const int shift = (ty - 1) * 26 + (tx - 1);
        const uint32_t St = sbase + (uint32_t)(c % 3) * STAGE_B;
        const __half* asrc = g_xs + (arow_noshift + shift) * KPRIME + kc + aq * 16;
        const __half* bsrc = g_wb + ((size_t)(tap * 256 + brow)) * KPRIME + kc + bh * 32;
#pragma unroll
        for (int g = 0; g < 2; g++) CP_ASYNC16(St + sdstA[g], asrc + g * 8);
#pragma unroll
        for (int g = 0; g < 4; g++) CP_ASYNC16(St + sdstB[g], bsrc + g * 8);
    };

    auto compute = [&](int c) {
        const uint32_t St = sbase + (uint32_t)(c % 3) * STAGE_B;
#pragma unroll
        for (int ks = 0; ks < 4; ks++) {
            const uint32_t off = (((uint32_t)(ks * 2) + kHi) ^ rsw) << 4;
            uint32_t a[2][4], b[4][4];
#pragma unroll
            for (int mi = 0; mi < 2; mi++) ldsm_x4(a[mi], St + aRow[mi] + off);
#pragma unroll
            for (int gi = 0; gi < 4; gi++) ldsm_x4(b[gi], St + bRow[gi] + off);
#pragma unroll
            for (int mi = 0; mi < 2; mi++)
#pragma unroll
                for (int gi = 0; gi < 4; gi++) {
                    mma_f16(acc[mi][gi * 2 + 0], a[mi], b[gi][0], b[gi][2]);
                    mma_f16(acc[mi][gi * 2 + 1], a[mi], b[gi][1], b[gi][3]);
                }
        }
    };

    issue(0); CP_COMMIT();
    issue(1); CP_COMMIT();
    for (int c = 0; c < N_CHUNKS; ++c) {
        if (c < N_CHUNKS - 1) { CP_WAIT(1); } else { CP_WAIT(0); }
        __syncthreads();
        if (c + 2 < N_CHUNKS) { issue(c + 2); CP_COMMIT(); }
        compute(c);
    }

    // ---- epilogue: BN + ReLU, drop padded rows, write g_x1 (NCHW) ----
    bool mvalid[4];
    float* mptr[4];
#pragma unroll
    for (int mi = 0; mi < 2; mi++)
#pragma unroll
        for (int h = 0; h < 2; h++) {
            int i = mi * 2 + h;
            int mg = m0 + wm + mi * 16 + (l >> 2) + h * 8;
            int plane = mg / 676;
            int pos = mg - plane * 676;
            int yq = pos / 26, xq = pos - yq * 26;
            mvalid[i] = (yq >= 1 && yq <= 24 && xq >= 1 && xq <= 24);
            mptr[i] = g_x1 + (size_t)plane * 147456 + (yq - 1) * 24 + (xq - 1);
        }
#pragma unroll
    for (int ni = 0; ni < 8; ni++) {
        int n0 = wn + (ni >> 1) * 16 + (ni & 1) * 8 + (l & 3) * 2;
        float sc0 = g_scale[n0], sh0 = g_shift[n0];
        float sc1 = g_scale[n0 + 1], sh1 = g_shift[n0 + 1];
#pragma unroll
        for (int mi = 0; mi < 2; mi++)
#pragma unroll
            for (int h = 0; h < 2; h++) {
                int i = mi * 2 + h;
                if (!mvalid[i]) continue;
                float v0 = fmaf(acc[mi][ni][h * 2 + 0], sc0, sh0);
                float v1 = fmaf(acc[mi][ni][h * 2 + 1], sc1, sh1);
                mptr[i][(size_t)n0 * 576] = fmaxf(v0, 0.f);
                mptr[i][(size_t)(n0 + 1) * 576] = fmaxf(v1, 0.f);
            }
    }
}

// ---------------- conv2 (1x1, 256->25) + bias + softmax ----------------
__global__ __launch_bounds__(128) void conv2_kernel(const float* __restrict__ w2,
                                                    const float* __restrict__ b2) {
    __shared__ float As[16][128];
    __shared__ float Bs[16][25];
    __shared__ float b2s[25];

    const int t = threadIdx.x;
    const int m = blockIdx.x * 128 + t;
    const int b = m / 576;
    const int pos = m - b * 576;
    const float* xp = g_x1 + (size_t)b * 147456 + pos;

    if (t < 25) b2s[t] = b2[t];

    float acc[25];
#pragma unroll
    for (int n = 0; n < 25; n++) acc[n] = 0.f;

    for (int kc = 0; kc < 256; kc += 16) {
#pragma unroll
        for (int kk = 0; kk < 16; kk++) As[kk][t] = xp[(size_t)(kc + kk) * 576];
        for (int e = t; e < 400; e += 128) {
            int k = e / 25;
            int n = e - k * 25;
            Bs[k][n] = w2[n * 256 + kc + k];
        }
        __syncthreads();
#pragma unroll
        for (int kk = 0; kk < 16; kk++) {
            float a = As[kk][t];
#pragma unroll
            for (int n = 0; n < 25; n++) acc[n] = fmaf(a, Bs[kk][n], acc[n]);
        }
        __syncthreads();
    }

    float mx = -1e30f;
#pragma unroll
    for (int n = 0; n < 25; n++) { acc[n] += b2s[n]; mx = fmaxf(mx, acc[n]); }
    float sum = 0.f;
#pragma unroll
    for (int n = 0; n < 25; n++) { acc[n] = __expf(acc[n] - mx); sum += acc[n]; }
    float inv = 1.f / sum;

    float* kp = g_kmap + (size_t)b * 14400 + pos;
#pragma unroll
    for (int n = 0; n < 25; n++) kp[(size_t)n * 576] = acc[n] * inv;
}

// ---------------- 25-tap propagation (channel-split grid) ----------------
#define CSPLIT 8
#define CPB    32

__global__ __launch_bounds__(192) void prop_kernel(const float* __restrict__ src,
                                                   float* __restrict__ out) {
    __shared__ float patch[2][336];

    const int t = threadIdx.x;
    const int blk = blockIdx.x;
    const int cs = blk & (CSPLIT - 1);
    const int brg = blk >> 3;
    const int b = brg / 3;
    const int rg = brg - b * 3;
    const int pos0 = rg * 192;
    const int y0 = rg * 8;
    const int c0 = cs * CPB;

    float pr[25];
    const float* kp = g_kmap + (size_t)b * 14400 + pos0 + t;
#pragma unroll
    for (int n = 0; n < 25; n++) pr[n] = kp[(size_t)n * 576];

    int off[2];
    bool val[2];
#pragma unroll
    for (int i = 0; i < 2; i++) {
        int e = t + i * 192;
        int ry = e / 28;
        int rx = e - ry * 28;
        int iy = y0 - 2 + ry;
        int ix = rx - 2;
        val[i] = (e < 336) && iy >= 0 && iy < 24 && ix >= 0 && ix < 24;
        off[i] = val[i] ? iy * 24 + ix : 0;
    }

    const float* sb = src + (size_t)b * 147456 + (size_t)c0 * 576;
    const int py = t / 24 + 2;
    const int px = t - (t / 24) * 24 + 2;
    const int pcenter = py * 28 + px;
    float* ob = out + (size_t)b * 147456 + (size_t)c0 * 576 + pos0 + t;

#pragma unroll
    for (int i = 0; i < 2; i++) {
        int e = t + i * 192;
        if (e < 336) patch[0][e] = val[i] ? sb[off[i]] : 0.f;
    }
    __syncthreads();

    for (int c = 0; c < CPB; ++c) {
        float nv[2];
        if (c + 1 < CPB) {
#pragma unroll
            for (int i = 0; i < 2; i++)
                nv[i] = val[i] ? sb[(size_t)(c + 1) * 576 + off[i]] : 0.f;
        }
        const float* pc = &patch[c & 1][0];
        float sum = 0.f;
#pragma unroll
        for (int o = 0; o < 25; o++) {
            int ddy = o / 5 - 2;
            int ddx = o - (o / 5) * 5 - 2;
            sum = fmaf(pc[pcenter + ddy * 28 + ddx], pr[o], sum);
        }
        ob[(size_t)c * 576] = sum;

        if (c + 1 < CPB) {
#pragma unroll
            for (int i = 0; i < 2; i++) {
                int e = t + i * 192;
                if (e < 336) patch[(c + 1) & 1][e] = nv[i];
            }
        }
        __syncthreads();
    }
}

// ---------------- launcher ----------------
extern "C" void kernel_launch(void* const* d_in, const int* in_sizes, int n_in,
                              void* d_out, int out_size) {
    const float* src = (const float*)d_in[0];
    const float* det = (const float*)d_in[1];
    const float* w1  = (const float*)d_in[2];
    const float* b1  = (const float*)d_in[3];
    const float* gam = (const float*)d_in[4];
    const float* bet = (const float*)d_in[5];
    const float* mu  = (const float*)d_in[6];
    const float* var = (const float*)d_in[7];
    const float* w2  = (const float*)d_in[8];
    const float* b2  = (const float*)d_in[9];
    float* out = (float*)d_out;

    cudaFuncSetAttribute(conv1_mma, cudaFuncAttributeMaxDynamicSharedMemorySize, CONV1_SMEM);

    snprep_kernel<<<1, 256>>>(b1, gam, bet, mu, var);
    wprep_kernel<<<(9 * 256 * KPRIME + 255) / 256, 256>>>(w1);
    xprep_kernel<<<130 * 26, 256>>>(src, det);

    conv1_mma<<<676, 512, CONV1_SMEM>>>();

    conv2_kernel<<<576, 128>>>(w2, b2);
    prop_kernel<<<128 * 3 * CSPLIT, 192>>>(src, out);
}